// round 3
// baseline (speedup 1.0000x reference)
#include <cuda_runtime.h>
#include <cstdint>

// EmbedWeighted == out(B,D) = inputs(B,V) @ embeddings(V,D)
#define B_DIM 2048
#define V_DIM 2000
#define D_DIM 64
#define NSPLIT 8
#define KSPLIT 256          // splits 0..6: 256, split 7: 208
#define KC 32               // k-chunk per pipeline stage
#define NSTAGE 3
#define A_STRIDE 36         // 4 mod 32 -> conflict-free frag loads
#define E_STRIDE 72         // 8 mod 32 -> conflict-free frag loads
#define ABUF (128 * A_STRIDE)
#define EBUF (KC * E_STRIDE)
#define SMEM_BYTES (NSTAGE * (ABUF + EBUF) * 4)
#define NTHREADS 512

__device__ float g_partials[NSPLIT][B_DIM][D_DIM];   // 4 MB static scratch
__device__ unsigned int g_arrive[B_DIM / 128];       // zero-init, self-resetting
__device__ unsigned int g_done[B_DIM / 128];

__device__ __forceinline__ uint32_t f2tf32(float f) {
    uint32_t r;
    asm("cvt.rna.tf32.f32 %0, %1;" : "=r"(r) : "f"(f));
    return r;
}

__device__ __forceinline__ void cp_async16(float* dst_smem, const float* src, bool pred) {
    uint32_t d = (uint32_t)__cvta_generic_to_shared(dst_smem);
    int sz = pred ? 16 : 0;   // src-size 0 => zero-fill 16B
    asm volatile("cp.async.cg.shared.global [%0], [%1], 16, %2;"
                 :: "r"(d), "l"(src), "r"(sz));
}
__device__ __forceinline__ void cp_commit() {
    asm volatile("cp.async.commit_group;");
}
template <int N>
__device__ __forceinline__ void cp_wait() {
    asm volatile("cp.async.wait_group %0;" :: "n"(N));
}

// Issue one KC-wide stage: A 128x32 fp32, E 32x64 fp32. Commits one group.
__device__ __forceinline__ void stage_load(const float* __restrict__ inpS,
                                           const float* __restrict__ embS,
                                           float* __restrict__ As, float* __restrict__ Es,
                                           int kc, int k_len, int tid)
{
    // A: 1024 16B chunks, 2 per thread
    #pragma unroll
    for (int i = 0; i < 2; i++) {
        int idx = tid + i * NTHREADS;
        int r = idx >> 3, q = idx & 7;
        int k = kc + q * 4;
        bool p = (k < k_len);                // k_len multiple of 16 -> whole-chunk validity
        cp_async16(As + r * A_STRIDE + q * 4,
                   inpS + (size_t)r * V_DIM + (p ? k : 0), p);
    }
    // E: 512 16B chunks, 1 per thread
    {
        int r = tid >> 4, q = tid & 15;
        int k = kc + r;
        bool p = (k < k_len);
        cp_async16(Es + r * E_STRIDE + q * 4,
                   embS + (size_t)(p ? k : 0) * D_DIM + q * 4, p);
    }
    cp_commit();
}

// 512 threads, 16 warps, warp tile 32x16. CTA tile M=128, N=64. grid (8,16) = one wave.
__global__ __launch_bounds__(NTHREADS, 1)
void embedweighted_fused(const float* __restrict__ inp,
                         const float* __restrict__ emb,
                         float* __restrict__ out)
{
    extern __shared__ float smem[];
    float* As = smem;                     // NSTAGE buffers
    float* Es = smem + NSTAGE * ABUF;     // NSTAGE buffers

    const int ksplit = blockIdx.x;
    const int mtile  = blockIdx.y;
    const int m_base = mtile * 128;
    const int k_base = ksplit * KSPLIT;
    const int k_len  = (ksplit < NSPLIT - 1) ? KSPLIT : (V_DIM - (NSPLIT - 1) * KSPLIT);
    const int nstages = (k_len + KC - 1) / KC;

    const float* inpS = inp + (size_t)m_base * V_DIM + k_base;
    const float* embS = emb + (size_t)k_base * D_DIM;

    const int tid  = threadIdx.x;
    const int warp = tid >> 5;
    const int lane = tid & 31;
    const int g = lane >> 2;          // 0..7
    const int t = lane & 3;           // 0..3
    const int warp_m = warp & 3;      // 32-row slab
    const int warp_n = warp >> 2;     // 16-col slab (0..3)

    float acc[2][2][4];
    #pragma unroll
    for (int i = 0; i < 2; i++)
        #pragma unroll
        for (int j = 0; j < 2; j++)
            #pragma unroll
            for (int r = 0; r < 4; r++) acc[i][j][r] = 0.0f;

    // ---- prologue: fill 2 of 3 stages ----
    stage_load(inpS, embS, As, Es, 0, k_len, tid);
    stage_load(inpS, embS, As + ABUF, Es + EBUF, KC, k_len, tid);

    // ---- mainloop: one barrier per stage ----
    for (int it = 0; it < nstages; it++) {
        cp_wait<1>();         // group `it` complete (exactly 2 newer may pend)
        __syncthreads();      // data visible CTA-wide; also WAR fence for slot (it+2)%3

        // prefetch stage it+2 into the slot freed at compute(it-1) [pre-barrier]
        int wslot = (it + 2) % NSTAGE;
        if (it + 2 < nstages)
            stage_load(inpS, embS, As + wslot * ABUF, Es + wslot * EBUF,
                       (it + 2) * KC, k_len, tid);
        else
            cp_commit();      // empty group keeps wait_group accounting uniform

        const float* Ab = As + (it % NSTAGE) * ABUF;
        const float* Eb = Es + (it % NSTAGE) * EBUF;
        #pragma unroll
        for (int kk = 0; kk < KC; kk += 8) {
            uint32_t a[2][4], b[2][2];
            #pragma unroll
            for (int mt = 0; mt < 2; mt++) {
                int m0 = warp_m * 32 + mt * 16;
                // raw fp32 bits: tf32 MMA reads top 19 bits (RZ truncation)
                a[mt][0] = __float_as_uint(Ab[(m0 + g)     * A_STRIDE + kk + t]);
                a[mt][1] = __float_as_uint(Ab[(m0 + g + 8) * A_STRIDE + kk + t]);
                a[mt][2] = __float_as_uint(Ab[(m0 + g)     * A_STRIDE + kk + t + 4]);
                a[mt][3] = __float_as_uint(Ab[(m0 + g + 8) * A_STRIDE + kk + t + 4]);
            }
            #pragma unroll
            for (int nt = 0; nt < 2; nt++) {
                int n0 = warp_n * 16 + nt * 8;
                b[nt][0] = f2tf32(Eb[(kk + t)     * E_STRIDE + n0 + g]);
                b[nt][1] = f2tf32(Eb[(kk + t + 4) * E_STRIDE + n0 + g]);
            }
            #pragma unroll
            for (int mt = 0; mt < 2; mt++)
                #pragma unroll
                for (int nt = 0; nt < 2; nt++)
                    asm volatile(
                        "mma.sync.aligned.m16n8k8.row.col.f32.tf32.tf32.f32 "
                        "{%0,%1,%2,%3}, {%4,%5,%6,%7}, {%8,%9}, {%0,%1,%2,%3};"
                        : "+f"(acc[mt][nt][0]), "+f"(acc[mt][nt][1]),
                          "+f"(acc[mt][nt][2]), "+f"(acc[mt][nt][3])
                        : "r"(a[mt][0]), "r"(a[mt][1]), "r"(a[mt][2]), "r"(a[mt][3]),
                          "r"(b[nt][0]), "r"(b[nt][1]));
        }
    }

    // ---- write 128x64 fp32 partial tile ----
    float* pp = &g_partials[ksplit][m_base][0];
    #pragma unroll
    for (int mt = 0; mt < 2; mt++) {
        int m0 = warp_m * 32 + mt * 16;
        #pragma unroll
        for (int nt = 0; nt < 2; nt++) {
            int n0 = warp_n * 16 + nt * 8 + 2 * t;
            pp[(m0 + g)     * D_DIM + n0]     = acc[mt][nt][0];
            pp[(m0 + g)     * D_DIM + n0 + 1] = acc[mt][nt][1];
            pp[(m0 + g + 8) * D_DIM + n0]     = acc[mt][nt][2];
            pp[(m0 + g + 8) * D_DIM + n0 + 1] = acc[mt][nt][3];
        }
    }

    // ---- fused deterministic split-K reduction (all 128 CTAs co-resident) ----
    __syncthreads();
    if (tid == 0) {
        __threadfence();                       // release this CTA's partial stores
        atomicAdd(&g_arrive[mtile], 1u);
        unsigned v;
        do {
            asm volatile("ld.acquire.gpu.u32 %0, [%1];" : "=r"(v) : "l"(&g_arrive[mtile]));
            if (v >= NSPLIT) break;
            __nanosleep(64);
        } while (true);
    }
    __syncthreads();   // propagate tid0's acquire to the CTA

    // This CTA reduces rows [m_base + ksplit*16, +16): 256 float4.
    if (tid < 256) {
        int r = tid >> 4, q = tid & 15;
        int off = (m_base + ksplit * 16 + r) * (D_DIM / 4) + q;
        const float4* p = reinterpret_cast<const float4*>(&g_partials[0][0][0]);
        float4 s = p[off];
        #pragma unroll
        for (int sp = 1; sp < NSPLIT; sp++) {   // fixed order -> deterministic
            float4 v = p[(size_t)sp * (B_DIM * D_DIM / 4) + off];
            s.x += v.x; s.y += v.y; s.z += v.z; s.w += v.w;
        }
        reinterpret_cast<float4*>(out)[off] = s;
    }

    // reset counters for graph replay
    __syncthreads();
    if (tid == 0) {
        unsigned d = atomicAdd(&g_done[mtile], 1u);
        if (d == NSPLIT - 1) {
            atomicExch(&g_arrive[mtile], 0u);
            atomicExch(&g_done[mtile], 0u);
        }
    }
}

extern "C" void kernel_launch(void* const* d_in, const int* in_sizes, int n_in,
                              void* d_out, int out_size)
{
    const float* inputs     = (const float*)d_in[0];   // (B, V) fp32
    const float* embeddings = (const float*)d_in[1];   // (V, D) fp32
    float* out = (float*)d_out;                        // (B, D) fp32

    cudaFuncSetAttribute(embedweighted_fused,
                         cudaFuncAttributeMaxDynamicSharedMemorySize, SMEM_BYTES);

    dim3 grid(NSPLIT, B_DIM / 128);   // 128 CTAs == one wave (<=148 SMs)
    embedweighted_fused<<<grid, NTHREADS, SMEM_BYTES>>>(inputs, embeddings, out);
}